// round 11
// baseline (speedup 1.0000x reference)
#include <cuda_runtime.h>
#include <cstdint>

#define NN 25000
#define PP 100000
#define LEAKYF 0.001f

// ---- device scratch (allocation-free rule: __device__ globals) ----
__device__ float g_Epre[4 * NN * 128];   // 51.2 MB: E[k][n][j] = enc[n] @ W0_block_k

__device__ __forceinline__ float lk(float x) { return fmaxf(x, LEAKYF * x); }

// ---- packed f32x2 helpers (Blackwell FFMA2 path) ----
__device__ __forceinline__ unsigned long long dup2(float x) {
    unsigned long long r;
    unsigned u = __float_as_uint(x);
    asm("mov.b64 %0, {%1, %1};" : "=l"(r) : "r"(u));
    return r;
}
__device__ __forceinline__ unsigned long long pk2(float lo, float hi) {
    unsigned long long r;
    asm("mov.b64 %0, {%1, %2};" : "=l"(r) : "r"(__float_as_uint(lo)), "r"(__float_as_uint(hi)));
    return r;
}
__device__ __forceinline__ void fma2(unsigned long long& d,
                                     unsigned long long a, unsigned long long b) {
    asm("fma.rn.f32x2 %0, %1, %2, %0;" : "+l"(d) : "l"(a), "l"(b));
}
__device__ __forceinline__ float2 up2(unsigned long long v) {
    unsigned lo, hi;
    asm("mov.b64 {%0, %1}, %2;" : "=r"(lo), "=r"(hi) : "l"(v));
    return make_float2(__uint_as_float(lo), __uint_as_float(hi));
}

// ---- smem layout (float offsets) for main kernel ----
#define OFF_W1   0        // 16384
#define OFF_W2   16384    // 16384
#define OFF_W0T  32768    // 512  (W0 rows 512..515: t, sin, cos, dl)
#define OFF_B0   33280    // 128
#define OFF_B1   33408    // 128
#define OFF_B2   33536    // 128
#define OFF_W3   33664    // 256
#define OFF_B3   33920    // 2
#define OFF_TS   33924    // 4
#define OFF_DELT 33928    // 8 warps * 32
#define OFF_META 34184    // 8 warps * 128
#define OFF_HBUF 35208    // 8 warps * 8 pairs * 256 (pair-interleaved h)
#define SMEM_FLOATS (OFF_HBUF + 8*8*256)   // 51592 floats = 206368 B

// ---- Epre: E[k][n][:] = encoded[n][:] @ W0[k*128:(k+1)*128, :] (FFMA2 packed) ----
__global__ void __launch_bounds__(256) epre_kernel(
    const float* __restrict__ enc, const float* __restrict__ W0)
{
    const int k = blockIdx.y;
    const int warp = threadIdx.x >> 5, lane = threadIdx.x & 31;
    const int n0 = blockIdx.x * 64 + warp * 8;
    const float* Wk = W0 + k * 128 * 128;

    unsigned long long acc[4][4];
    #pragma unroll
    for (int p = 0; p < 4; p++)
        #pragma unroll
        for (int c = 0; c < 4; c++) acc[p][c] = 0ull;

    int nr[8];
    #pragma unroll
    for (int j = 0; j < 8; j++) nr[j] = min(n0 + j, NN - 1);

    #pragma unroll 1
    for (int i = 0; i < 128; i += 4) {
        float4 w0 = __ldg((const float4*)(Wk + (i + 0) * 128) + lane);
        float4 w1 = __ldg((const float4*)(Wk + (i + 1) * 128) + lane);
        float4 w2 = __ldg((const float4*)(Wk + (i + 2) * 128) + lane);
        float4 w3 = __ldg((const float4*)(Wk + (i + 3) * 128) + lane);
        unsigned long long d00 = dup2(w0.x), d01 = dup2(w0.y), d02 = dup2(w0.z), d03 = dup2(w0.w);
        unsigned long long d10 = dup2(w1.x), d11 = dup2(w1.y), d12 = dup2(w1.z), d13 = dup2(w1.w);
        unsigned long long d20 = dup2(w2.x), d21 = dup2(w2.y), d22 = dup2(w2.z), d23 = dup2(w2.w);
        unsigned long long d30 = dup2(w3.x), d31 = dup2(w3.y), d32 = dup2(w3.z), d33 = dup2(w3.w);
        #pragma unroll
        for (int p = 0; p < 4; p++) {
            float4 e0 = __ldg((const float4*)(enc + nr[2 * p] * 128 + i));
            float4 e1 = __ldg((const float4*)(enc + nr[2 * p + 1] * 128 + i));
            unsigned long long hx = pk2(e0.x, e1.x), hy = pk2(e0.y, e1.y);
            unsigned long long hz = pk2(e0.z, e1.z), hw = pk2(e0.w, e1.w);
            fma2(acc[p][0], hx, d00); fma2(acc[p][1], hx, d01); fma2(acc[p][2], hx, d02); fma2(acc[p][3], hx, d03);
            fma2(acc[p][0], hy, d10); fma2(acc[p][1], hy, d11); fma2(acc[p][2], hy, d12); fma2(acc[p][3], hy, d13);
            fma2(acc[p][0], hz, d20); fma2(acc[p][1], hz, d21); fma2(acc[p][2], hz, d22); fma2(acc[p][3], hz, d23);
            fma2(acc[p][0], hw, d30); fma2(acc[p][1], hw, d31); fma2(acc[p][2], hw, d32); fma2(acc[p][3], hw, d33);
        }
    }
    #pragma unroll
    for (int p = 0; p < 4; p++) {
        float2 f0 = up2(acc[p][0]), f1 = up2(acc[p][1]);
        float2 f2 = up2(acc[p][2]), f3 = up2(acc[p][3]);
        int na = n0 + 2 * p, nb = na + 1;
        if (na < NN) ((float4*)g_Epre)[((size_t)k * NN + na) * 32 + lane] =
            make_float4(f0.x, f1.x, f2.x, f3.x);
        if (nb < NN) ((float4*)g_Epre)[((size_t)k * NN + nb) * 32 + lane] =
            make_float4(f0.y, f1.y, f2.y, f3.y);
    }
}

// ---- packed 128x128 matvec layer: 16 rows (8 row-pairs) per warp via FFMA2 ----
// hp: pair-interleaved activations: hp[p*256 + 2*i + {0,1}] = (h_{2p}[i], h_{2p+1}[i])
__device__ __forceinline__ void layer_mv2(const float* __restrict__ Ws,
                                          const float* __restrict__ hp,
                                          int lane,
                                          const unsigned long long* bd, // [4] dup'd bias
                                          unsigned long long A2[8][4])
{
    #pragma unroll
    for (int p = 0; p < 8; p++)
        #pragma unroll
        for (int c = 0; c < 4; c++) A2[p][c] = bd[c];

    #pragma unroll 1
    for (int i = 0; i < 128; i += 4) {
        const float4* wp4 = (const float4*)(Ws + i * 128);
        float4 w0 = wp4[lane];
        float4 w1 = wp4[32 + lane];
        float4 w2 = wp4[64 + lane];
        float4 w3 = wp4[96 + lane];
        {
            unsigned long long d00 = dup2(w0.x), d01 = dup2(w0.y), d02 = dup2(w0.z), d03 = dup2(w0.w);
            unsigned long long d10 = dup2(w1.x), d11 = dup2(w1.y), d12 = dup2(w1.z), d13 = dup2(w1.w);
            #pragma unroll
            for (int p = 0; p < 8; p++) {
                ulonglong2 hA = *(const ulonglong2*)(hp + p * 256 + 2 * i);   // feats i, i+1
                fma2(A2[p][0], hA.x, d00); fma2(A2[p][1], hA.x, d01);
                fma2(A2[p][2], hA.x, d02); fma2(A2[p][3], hA.x, d03);
                fma2(A2[p][0], hA.y, d10); fma2(A2[p][1], hA.y, d11);
                fma2(A2[p][2], hA.y, d12); fma2(A2[p][3], hA.y, d13);
            }
        }
        {
            unsigned long long d20 = dup2(w2.x), d21 = dup2(w2.y), d22 = dup2(w2.z), d23 = dup2(w2.w);
            unsigned long long d30 = dup2(w3.x), d31 = dup2(w3.y), d32 = dup2(w3.z), d33 = dup2(w3.w);
            #pragma unroll
            for (int p = 0; p < 8; p++) {
                ulonglong2 hB = *(const ulonglong2*)(hp + p * 256 + 2 * i + 4); // feats i+2, i+3
                fma2(A2[p][0], hB.x, d20); fma2(A2[p][1], hB.x, d21);
                fma2(A2[p][2], hB.x, d22); fma2(A2[p][3], hB.x, d23);
                fma2(A2[p][0], hB.y, d30); fma2(A2[p][1], hB.y, d31);
                fma2(A2[p][2], hB.y, d32); fma2(A2[p][3], hB.y, d33);
            }
        }
    }
}

// E-table gather macro: accumulate 4 table rows for one proper's int4 indices
#define GATH(bq, Pq) do { \
    float4 e; \
    e = __ldg(&E4[((size_t)0 * NN + (Pq).x) * 32 + lane]); bq.x += e.x; bq.y += e.y; bq.z += e.z; bq.w += e.w; \
    e = __ldg(&E4[((size_t)1 * NN + (Pq).y) * 32 + lane]); bq.x += e.x; bq.y += e.y; bq.z += e.z; bq.w += e.w; \
    e = __ldg(&E4[((size_t)2 * NN + (Pq).z) * 32 + lane]); bq.x += e.x; bq.y += e.y; bq.z += e.z; bq.w += e.w; \
    e = __ldg(&E4[((size_t)3 * NN + (Pq).w) * 32 + lane]); bq.x += e.x; bq.y += e.y; bq.z += e.z; bq.w += e.w; \
} while (0)

__global__ void __launch_bounds__(256, 1) main_kernel(
    const float* __restrict__ coords,
    const int* __restrict__ propers,      // int32 (JAX x64 off)
    const float* __restrict__ tarr,
    const float* __restrict__ W0,
    const float* __restrict__ b0,
    const float* __restrict__ W1,
    const float* __restrict__ b1,
    const float* __restrict__ W2,
    const float* __restrict__ b2,
    const float* __restrict__ W3,
    const float* __restrict__ b3,
    float* __restrict__ out)
{
    extern __shared__ float sm[];
    const int tid = threadIdx.x;

    // cooperative weight staging
    float4* s4 = (float4*)sm;
    for (int i = tid; i < 4096; i += 256) s4[i]        = ((const float4*)W1)[i];
    for (int i = tid; i < 4096; i += 256) s4[4096 + i] = ((const float4*)W2)[i];
    for (int i = tid; i < 128;  i += 256) s4[8192 + i] = ((const float4*)(W0 + 512 * 128))[i];
    if (tid < 32) {
        s4[8320 + tid] = ((const float4*)b0)[tid];
        s4[8352 + tid] = ((const float4*)b1)[tid];
        s4[8384 + tid] = ((const float4*)b2)[tid];
    }
    if (tid < 64) s4[8416 + tid] = ((const float4*)W3)[tid];
    if (tid < 2)  sm[OFF_B3 + tid] = b3[tid];
    if (tid < 4)  sm[OFF_TS + tid] = tarr[tid];
    __syncthreads();

    const int warp = tid >> 5, lane = tid & 31;
    float* hp   = sm + OFF_HBUF + warp * 2048;
    float* meta = sm + OFF_META + warp * 128;
    float* dbuf = sm + OFF_DELT + warp * 32;
    const float4* E4 = (const float4*)g_Epre;

    // per-lane constant weight slices (held in registers across iterations)
    float4 wt  = ((const float4*)(sm + OFF_W0T      ))[lane];
    float4 wsn = ((const float4*)(sm + OFF_W0T + 128))[lane];
    float4 wcs = ((const float4*)(sm + OFF_W0T + 256))[lane];
    float4 wdl = ((const float4*)(sm + OFF_W0T + 384))[lane];
    float4 b0v = ((const float4*)(sm + OFF_B0))[lane];
    float4 b1v = ((const float4*)(sm + OFF_B1))[lane];
    float4 b2v = ((const float4*)(sm + OFF_B2))[lane];
    float4 w3a = ((const float4*)(sm + OFF_W3))[2 * lane];
    float4 w3b = ((const float4*)(sm + OFF_W3))[2 * lane + 1];
    float  b30 = sm[OFF_B3], b31 = sm[OFF_B3 + 1];

    unsigned long long b1d[4] = { dup2(b1v.x), dup2(b1v.y), dup2(b1v.z), dup2(b1v.w) };
    unsigned long long b2d[4] = { dup2(b2v.x), dup2(b2v.y), dup2(b2v.z), dup2(b2v.w) };

    // static partition: each warp handles 4 propers (16 rows) per loop trip
    const int gw = blockIdx.x * 8 + warp;
    const int stride = gridDim.x * 8 * 4;

    for (int pbase = gw * 4; pbase < PP; pbase += stride) {
        const int* pr = propers + (size_t)pbase * 4;
        int4 P0 = ((const int4*)pr)[0];
        int4 P1 = ((const int4*)pr)[1];
        int4 P2 = ((const int4*)pr)[2];
        int4 P3 = ((const int4*)pr)[3];

        // --- geometry: lane r (<16) handles row r = (proper q = r>>2, t = r&3) ---
        if (lane < 16) {
            const int q = lane >> 2, tt = lane & 3;
            int4 Ps = (q == 0) ? P0 : (q == 1) ? P1 : (q == 2) ? P2 : P3;
            const float* C0 = coords + (Ps.x * 4 + tt) * 3;
            const float* C1 = coords + (Ps.y * 4 + tt) * 3;
            const float* C2 = coords + (Ps.z * 4 + tt) * 3;
            const float* C3 = coords + (Ps.w * 4 + tt) * 3;
            float c0x = C0[0], c0y = C0[1], c0z = C0[2];
            float c1x = C1[0], c1y = C1[1], c1z = C1[2];
            float c2x = C2[0], c2y = C2[1], c2z = C2[2];
            float c3x = C3[0], c3y = C3[1], c3z = C3[2];
            float u1x = c1x - c0x, u1y = c1y - c0y, u1z = c1z - c0z;
            float u2x = c2x - c1x, u2y = c2y - c1y, u2z = c2z - c1z;
            float u3x = c3x - c2x, u3y = c3y - c2y, u3z = c3z - c2z;
            float ax = u1y * u2z - u1z * u2y;
            float ay = u1z * u2x - u1x * u2z;
            float az = u1x * u2y - u1y * u2x;
            float bx = u2y * u3z - u2z * u3y;
            float by = u2z * u3x - u2x * u3z;
            float bz = u2x * u3y - u2y * u3x;
            float u2n = sqrtf(u2x * u2x + u2y * u2y + u2z * u2z);
            float yv = (u1x * bx + u1y * by + u1z * bz) * u2n;
            float xv = ax * bx + ay * by + az * bz;
            float rin = rsqrtf(fmaxf(xv * xv + yv * yv, 1e-30f));
            float drx = c0x - c3x, dry = c0y - c3y, drz = c0z - c3z;
            float dl = sqrtf(fmaxf(drx * drx + dry * dry + drz * drz, 1e-12f));
            float inv = 1.0f / dl;
            meta[lane * 8 + 0] = drx * inv;
            meta[lane * 8 + 1] = dry * inv;
            meta[lane * 8 + 2] = drz * inv;
            meta[lane * 8 + 3] = dl;
            meta[lane * 8 + 4] = yv * rin;          // sin(theta)
            meta[lane * 8 + 5] = xv * rin;          // cos(theta)
            meta[lane * 8 + 6] = sm[OFF_TS + tt];
        }

        // --- layer-0 base vectors: gather precomputed E tables (shared over T) ---
        float4 bb0 = b0v, bb1 = b0v, bb2 = b0v, bb3 = b0v;
        GATH(bb0, P0);
        GATH(bb1, P1);
        GATH(bb2, P2);
        GATH(bb3, P3);
        __syncwarp();

        // --- layer 0: scalar-feature terms + leaky; store pair-interleaved ---
        #pragma unroll
        for (int p = 0; p < 8; p++) {
            float4 bs = ((p >> 1) == 0) ? bb0 : ((p >> 1) == 1) ? bb1 : ((p >> 1) == 2) ? bb2 : bb3;
            float4 hr[2];
            #pragma unroll
            for (int s = 0; s < 2; s++) {
                int r = 2 * p + s;
                float dlr = meta[r * 8 + 3], snr = meta[r * 8 + 4];
                float csr = meta[r * 8 + 5], tvr = meta[r * 8 + 6];
                float4 q;
                q.x = fmaf(tvr, wt.x, fmaf(snr, wsn.x, fmaf(csr, wcs.x, fmaf(dlr, wdl.x, bs.x))));
                q.y = fmaf(tvr, wt.y, fmaf(snr, wsn.y, fmaf(csr, wcs.y, fmaf(dlr, wdl.y, bs.y))));
                q.z = fmaf(tvr, wt.z, fmaf(snr, wsn.z, fmaf(csr, wcs.z, fmaf(dlr, wdl.z, bs.z))));
                q.w = fmaf(tvr, wt.w, fmaf(snr, wsn.w, fmaf(csr, wcs.w, fmaf(dlr, wdl.w, bs.w))));
                hr[s] = make_float4(lk(q.x), lk(q.y), lk(q.z), lk(q.w));
            }
            *(float4*)(hp + p * 256 + 8 * lane)     = make_float4(hr[0].x, hr[1].x, hr[0].y, hr[1].y);
            *(float4*)(hp + p * 256 + 8 * lane + 4) = make_float4(hr[0].z, hr[1].z, hr[0].w, hr[1].w);
        }
        __syncwarp();

        // --- layer 1 (packed, 16 rows) ---
        unsigned long long A2[8][4];
        layer_mv2(sm + OFF_W1, hp, lane, b1d, A2);
        __syncwarp();
        #pragma unroll
        for (int p = 0; p < 8; p++) {
            float2 f0 = up2(A2[p][0]), f1 = up2(A2[p][1]);
            float2 f2 = up2(A2[p][2]), f3 = up2(A2[p][3]);
            *(float4*)(hp + p * 256 + 8 * lane)     = make_float4(lk(f0.x), lk(f0.y), lk(f1.x), lk(f1.y));
            *(float4*)(hp + p * 256 + 8 * lane + 4) = make_float4(lk(f2.x), lk(f2.y), lk(f3.x), lk(f3.y));
        }
        __syncwarp();

        // --- layer 2 (packed) ---
        layer_mv2(sm + OFF_W2, hp, lane, b2d, A2);

        // --- layer 3: 128 -> 2 warp reduction per row ---
        #pragma unroll
        for (int p = 0; p < 8; p++) {
            float2 f0 = up2(A2[p][0]), f1 = up2(A2[p][1]);
            float2 f2 = up2(A2[p][2]), f3 = up2(A2[p][3]);
            #pragma unroll
            for (int s = 0; s < 2; s++) {
                int r = 2 * p + s;
                float h0 = lk(s ? f0.y : f0.x), h1 = lk(s ? f1.y : f1.x);
                float h2 = lk(s ? f2.y : f2.x), h3 = lk(s ? f3.y : f3.x);
                float q0 = h0 * w3a.x + h1 * w3a.z + h2 * w3b.x + h3 * w3b.z;
                float q1 = h0 * w3a.y + h1 * w3a.w + h2 * w3b.y + h3 * w3b.w;
                #pragma unroll
                for (int off = 16; off > 0; off >>= 1) {
                    q0 += __shfl_xor_sync(0xffffffffu, q0, off);
                    q1 += __shfl_xor_sync(0xffffffffu, q1, off);
                }
                if (lane == 0) { dbuf[2 * r] = q0 + b30; dbuf[2 * r + 1] = q1 + b31; }
            }
        }
        __syncwarp();

        // --- scatter: 96 atomics (4 propers x 4 t x (2 endpoints x 3 comps)) ---
        #pragma unroll
        for (int a0 = 0; a0 < 96; a0 += 32) {
            int a = a0 + lane;
            int row = a / 6; int w6 = a - row * 6;
            int q = row >> 2, tt = row & 3;
            int4 Ps = (q == 0) ? P0 : (q == 1) ? P1 : (q == 2) ? P2 : P3;
            int comp = (w6 < 3) ? w6 : (w6 - 3);
            int tgt = (w6 < 3) ? Ps.x : Ps.w;
            float dval = (w6 < 3) ? (-0.5f * dbuf[2 * row]) : (0.5f * dbuf[2 * row + 1]);
            atomicAdd(out + (tgt * 4 + tt) * 3 + comp, dval * meta[row * 8 + comp]);
        }
        __syncwarp();
    }
}

extern "C" void kernel_launch(void* const* d_in, const int* in_sizes, int n_in,
                              void* d_out, int out_size)
{
    const float* coords  = (const float*)d_in[0];
    const int*   propers = (const int*)d_in[1];     // int32 (JAX x64 off)
    const float* encoded = (const float*)d_in[2];
    const float* tarr    = (const float*)d_in[3];
    const float* answer  = (const float*)d_in[4];
    const float* W0 = (const float*)d_in[5];
    const float* b0 = (const float*)d_in[6];
    const float* W1 = (const float*)d_in[7];
    const float* b1 = (const float*)d_in[8];
    const float* W2 = (const float*)d_in[9];
    const float* b2 = (const float*)d_in[10];
    const float* W3 = (const float*)d_in[11];
    const float* b3 = (const float*)d_in[12];
    float* out = (float*)d_out;

    int dev = 0;
    cudaGetDevice(&dev);
    int sms = 148;
    cudaDeviceGetAttribute(&sms, cudaDevAttrMultiProcessorCount, dev);

    cudaFuncSetAttribute(main_kernel, cudaFuncAttributeMaxDynamicSharedMemorySize,
                         SMEM_FLOATS * (int)sizeof(float));

    // out = answer (atomics accumulate on top)
    cudaMemcpyAsync(d_out, answer, (size_t)out_size * sizeof(float),
                    cudaMemcpyDeviceToDevice);

    dim3 eg((NN + 63) / 64, 4);
    epre_kernel<<<eg, 256>>>(encoded, W0);

    main_kernel<<<sms, 256, SMEM_FLOATS * (int)sizeof(float)>>>(
        coords, propers, tarr, W0, b0, W1, b1, W2, b2, W3, b3, out);
}

// round 15
// speedup vs baseline: 1.0837x; 1.0837x over previous
#include <cuda_runtime.h>
#include <cstdint>

#define NN 25000
#define PP 100000
#define LEAKYF 0.001f

// ---- device scratch (allocation-free rule: __device__ globals) ----
__device__ float g_Epre[4 * NN * 128];   // 51.2 MB: E[k][n][j] = enc[n] @ W0_block_k

__device__ __forceinline__ float lk(float x) { return fmaxf(x, LEAKYF * x); }

// ---- packed f32x2 helpers (Blackwell FFMA2 path) ----
__device__ __forceinline__ unsigned long long dup2(float x) {
    unsigned long long r;
    unsigned u = __float_as_uint(x);
    asm("mov.b64 %0, {%1, %1};" : "=l"(r) : "r"(u));
    return r;
}
__device__ __forceinline__ void fma2(unsigned long long& d,
                                     unsigned long long a, unsigned long long b) {
    asm("fma.rn.f32x2 %0, %1, %2, %0;" : "+l"(d) : "l"(a), "l"(b));
}
__device__ __forceinline__ float2 up2(unsigned long long v) {
    unsigned lo, hi;
    asm("mov.b64 {%0, %1}, %2;" : "=r"(lo), "=r"(hi) : "l"(v));
    return make_float2(__uint_as_float(lo), __uint_as_float(hi));
}

// ---- smem layout (float offsets) for main kernel ----
#define OFF_W1   0        // 16384
#define OFF_W2   16384    // 16384
#define OFF_W0T  32768    // 512  (W0 rows 512..515: t, sin, cos, dl)
#define OFF_B0   33280    // 128
#define OFF_B1   33408    // 128
#define OFF_B2   33536    // 128
#define OFF_W3   33664    // 256
#define OFF_B3   33920    // 2
#define OFF_TS   33924    // 4
#define OFF_DELT 33928    // 8 warps * 32
#define OFF_META 34184    // 8 warps * 128
#define OFF_HBUF 35208    // 8 warps * 8 pairs * 256 (pair-interleaved h)
#define SMEM_FLOATS (OFF_HBUF + 8*8*256)   // 51592 floats = 206368 B

#define MV4(A, hv, w0, w1, w2, w3) do { \
  (A).x = fmaf((hv).x,(w0).x, fmaf((hv).y,(w1).x, fmaf((hv).z,(w2).x, fmaf((hv).w,(w3).x,(A).x)))); \
  (A).y = fmaf((hv).x,(w0).y, fmaf((hv).y,(w1).y, fmaf((hv).z,(w2).y, fmaf((hv).w,(w3).y,(A).y)))); \
  (A).z = fmaf((hv).x,(w0).z, fmaf((hv).y,(w1).z, fmaf((hv).z,(w2).z, fmaf((hv).w,(w3).z,(A).z)))); \
  (A).w = fmaf((hv).x,(w0).w, fmaf((hv).y,(w1).w, fmaf((hv).z,(w2).w, fmaf((hv).w,(w3).w,(A).w)))); \
} while(0)

// ---- Epre: E[k][n][:] = encoded[n][:] @ W0[k*128:(k+1)*128, :] (R10 version) ----
__global__ void __launch_bounds__(256) epre_kernel(
    const float* __restrict__ enc, const float* __restrict__ W0)
{
    const int k = blockIdx.y;
    const int warp = threadIdx.x >> 5, lane = threadIdx.x & 31;
    const int n0 = blockIdx.x * 32 + warp * 4;
    const float* Wk = W0 + k * 128 * 128;

    float4 acc[4];
    #pragma unroll
    for (int r = 0; r < 4; r++) acc[r] = make_float4(0.f, 0.f, 0.f, 0.f);
    int nr[4];
    #pragma unroll
    for (int r = 0; r < 4; r++) nr[r] = min(n0 + r, NN - 1);

    #pragma unroll 1
    for (int i = 0; i < 128; i += 4) {
        float4 w0 = __ldg((const float4*)(Wk + (i + 0) * 128) + lane);
        float4 w1 = __ldg((const float4*)(Wk + (i + 1) * 128) + lane);
        float4 w2 = __ldg((const float4*)(Wk + (i + 2) * 128) + lane);
        float4 w3 = __ldg((const float4*)(Wk + (i + 3) * 128) + lane);
        #pragma unroll
        for (int r = 0; r < 4; r++) {
            float4 hv = __ldg((const float4*)(enc + nr[r] * 128 + i));
            MV4(acc[r], hv, w0, w1, w2, w3);
        }
    }
    #pragma unroll
    for (int r = 0; r < 4; r++) {
        int n = n0 + r;
        if (n < NN) ((float4*)g_Epre)[((size_t)k * NN + n) * 32 + lane] = acc[r];
    }
}

// ---- packed 128x128 matvec layer: 16 rows (8 row-pairs) per warp via FFMA2 ----
// hp: pair-interleaved activations: hp[p*256 + 2*i + {0,1}] = (h_{2p}[i], h_{2p+1}[i])
__device__ __forceinline__ void layer_mv2(const float* __restrict__ Ws,
                                          const float* __restrict__ hp,
                                          int lane,
                                          const unsigned long long* bd, // [4] dup'd bias
                                          unsigned long long A2[8][4])
{
    #pragma unroll
    for (int p = 0; p < 8; p++)
        #pragma unroll
        for (int c = 0; c < 4; c++) A2[p][c] = bd[c];

    #pragma unroll 1
    for (int i = 0; i < 128; i += 4) {
        const float4* wp4 = (const float4*)(Ws + i * 128);
        float4 w0 = wp4[lane];
        float4 w1 = wp4[32 + lane];
        float4 w2 = wp4[64 + lane];
        float4 w3 = wp4[96 + lane];
        {
            unsigned long long d00 = dup2(w0.x), d01 = dup2(w0.y), d02 = dup2(w0.z), d03 = dup2(w0.w);
            unsigned long long d10 = dup2(w1.x), d11 = dup2(w1.y), d12 = dup2(w1.z), d13 = dup2(w1.w);
            #pragma unroll
            for (int p = 0; p < 8; p++) {
                ulonglong2 hA = *(const ulonglong2*)(hp + p * 256 + 2 * i);   // feats i, i+1
                fma2(A2[p][0], hA.x, d00); fma2(A2[p][1], hA.x, d01);
                fma2(A2[p][2], hA.x, d02); fma2(A2[p][3], hA.x, d03);
                fma2(A2[p][0], hA.y, d10); fma2(A2[p][1], hA.y, d11);
                fma2(A2[p][2], hA.y, d12); fma2(A2[p][3], hA.y, d13);
            }
        }
        {
            unsigned long long d20 = dup2(w2.x), d21 = dup2(w2.y), d22 = dup2(w2.z), d23 = dup2(w2.w);
            unsigned long long d30 = dup2(w3.x), d31 = dup2(w3.y), d32 = dup2(w3.z), d33 = dup2(w3.w);
            #pragma unroll
            for (int p = 0; p < 8; p++) {
                ulonglong2 hB = *(const ulonglong2*)(hp + p * 256 + 2 * i + 4); // feats i+2, i+3
                fma2(A2[p][0], hB.x, d20); fma2(A2[p][1], hB.x, d21);
                fma2(A2[p][2], hB.x, d22); fma2(A2[p][3], hB.x, d23);
                fma2(A2[p][0], hB.y, d30); fma2(A2[p][1], hB.y, d31);
                fma2(A2[p][2], hB.y, d32); fma2(A2[p][3], hB.y, d33);
            }
        }
    }
}

// E-table gather macro: accumulate 4 table rows for one proper's int4 indices
#define GATH(bq, Pq) do { \
    float4 e; \
    e = __ldg(&E4[((size_t)0 * NN + (Pq).x) * 32 + lane]); bq.x += e.x; bq.y += e.y; bq.z += e.z; bq.w += e.w; \
    e = __ldg(&E4[((size_t)1 * NN + (Pq).y) * 32 + lane]); bq.x += e.x; bq.y += e.y; bq.z += e.z; bq.w += e.w; \
    e = __ldg(&E4[((size_t)2 * NN + (Pq).z) * 32 + lane]); bq.x += e.x; bq.y += e.y; bq.z += e.z; bq.w += e.w; \
    e = __ldg(&E4[((size_t)3 * NN + (Pq).w) * 32 + lane]); bq.x += e.x; bq.y += e.y; bq.z += e.z; bq.w += e.w; \
} while (0)

__global__ void __launch_bounds__(256, 1) main_kernel(
    const float* __restrict__ coords,
    const int* __restrict__ propers,      // int32 (JAX x64 off)
    const float* __restrict__ tarr,
    const float* __restrict__ W0,
    const float* __restrict__ b0,
    const float* __restrict__ W1,
    const float* __restrict__ b1,
    const float* __restrict__ W2,
    const float* __restrict__ b2,
    const float* __restrict__ W3,
    const float* __restrict__ b3,
    float* __restrict__ out)
{
    extern __shared__ float sm[];
    const int tid = threadIdx.x;

    // cooperative weight staging
    float4* s4 = (float4*)sm;
    for (int i = tid; i < 4096; i += 256) s4[i]        = ((const float4*)W1)[i];
    for (int i = tid; i < 4096; i += 256) s4[4096 + i] = ((const float4*)W2)[i];
    for (int i = tid; i < 128;  i += 256) s4[8192 + i] = ((const float4*)(W0 + 512 * 128))[i];
    if (tid < 32) {
        s4[8320 + tid] = ((const float4*)b0)[tid];
        s4[8352 + tid] = ((const float4*)b1)[tid];
        s4[8384 + tid] = ((const float4*)b2)[tid];
    }
    if (tid < 64) s4[8416 + tid] = ((const float4*)W3)[tid];
    if (tid < 2)  sm[OFF_B3 + tid] = b3[tid];
    if (tid < 4)  sm[OFF_TS + tid] = tarr[tid];
    __syncthreads();

    const int warp = tid >> 5, lane = tid & 31;
    float* hp   = sm + OFF_HBUF + warp * 2048;
    float* meta = sm + OFF_META + warp * 128;
    float* dbuf = sm + OFF_DELT + warp * 32;
    const float4* E4 = (const float4*)g_Epre;

    // per-lane constant weight slices (held in registers across iterations)
    float4 wt  = ((const float4*)(sm + OFF_W0T      ))[lane];
    float4 wsn = ((const float4*)(sm + OFF_W0T + 128))[lane];
    float4 wcs = ((const float4*)(sm + OFF_W0T + 256))[lane];
    float4 wdl = ((const float4*)(sm + OFF_W0T + 384))[lane];
    float4 b0v = ((const float4*)(sm + OFF_B0))[lane];
    float4 b1v = ((const float4*)(sm + OFF_B1))[lane];
    float4 b2v = ((const float4*)(sm + OFF_B2))[lane];
    float4 w3a = ((const float4*)(sm + OFF_W3))[2 * lane];
    float4 w3b = ((const float4*)(sm + OFF_W3))[2 * lane + 1];
    float  b30 = sm[OFF_B3], b31 = sm[OFF_B3 + 1];

    unsigned long long b1d[4] = { dup2(b1v.x), dup2(b1v.y), dup2(b1v.z), dup2(b1v.w) };
    unsigned long long b2d[4] = { dup2(b2v.x), dup2(b2v.y), dup2(b2v.z), dup2(b2v.w) };

    // static partition: each warp handles 4 propers (16 rows) per loop trip
    const int gw = blockIdx.x * 8 + warp;
    const int stride = gridDim.x * 8 * 4;

    for (int pbase = gw * 4; pbase < PP; pbase += stride) {
        const int* pr = propers + (size_t)pbase * 4;
        int4 P0 = ((const int4*)pr)[0];
        int4 P1 = ((const int4*)pr)[1];
        int4 P2 = ((const int4*)pr)[2];
        int4 P3 = ((const int4*)pr)[3];

        // --- geometry: lane r (<16) handles row r = (proper q = r>>2, t = r&3) ---
        if (lane < 16) {
            const int q = lane >> 2, tt = lane & 3;
            int4 Ps = (q == 0) ? P0 : (q == 1) ? P1 : (q == 2) ? P2 : P3;
            const float* C0 = coords + (Ps.x * 4 + tt) * 3;
            const float* C1 = coords + (Ps.y * 4 + tt) * 3;
            const float* C2 = coords + (Ps.z * 4 + tt) * 3;
            const float* C3 = coords + (Ps.w * 4 + tt) * 3;
            float c0x = C0[0], c0y = C0[1], c0z = C0[2];
            float c1x = C1[0], c1y = C1[1], c1z = C1[2];
            float c2x = C2[0], c2y = C2[1], c2z = C2[2];
            float c3x = C3[0], c3y = C3[1], c3z = C3[2];
            float u1x = c1x - c0x, u1y = c1y - c0y, u1z = c1z - c0z;
            float u2x = c2x - c1x, u2y = c2y - c1y, u2z = c2z - c1z;
            float u3x = c3x - c2x, u3y = c3y - c2y, u3z = c3z - c2z;
            float ax = u1y * u2z - u1z * u2y;
            float ay = u1z * u2x - u1x * u2z;
            float az = u1x * u2y - u1y * u2x;
            float bx = u2y * u3z - u2z * u3y;
            float by = u2z * u3x - u2x * u3z;
            float bz = u2x * u3y - u2y * u3x;
            float u2n = sqrtf(u2x * u2x + u2y * u2y + u2z * u2z);
            float yv = (u1x * bx + u1y * by + u1z * bz) * u2n;
            float xv = ax * bx + ay * by + az * bz;
            float rin = rsqrtf(fmaxf(xv * xv + yv * yv, 1e-30f));
            float drx = c0x - c3x, dry = c0y - c3y, drz = c0z - c3z;
            float dl = sqrtf(fmaxf(drx * drx + dry * dry + drz * drz, 1e-12f));
            float inv = 1.0f / dl;
            meta[lane * 8 + 0] = drx * inv;
            meta[lane * 8 + 1] = dry * inv;
            meta[lane * 8 + 2] = drz * inv;
            meta[lane * 8 + 3] = dl;
            meta[lane * 8 + 4] = yv * rin;          // sin(theta)
            meta[lane * 8 + 5] = xv * rin;          // cos(theta)
            meta[lane * 8 + 6] = sm[OFF_TS + tt];
        }

        // --- layer-0 base vectors: gather precomputed E tables (shared over T) ---
        float4 bb0 = b0v, bb1 = b0v, bb2 = b0v, bb3 = b0v;
        GATH(bb0, P0);
        GATH(bb1, P1);
        GATH(bb2, P2);
        GATH(bb3, P3);
        __syncwarp();

        // --- layer 0: scalar-feature terms + leaky; store pair-interleaved ---
        #pragma unroll
        for (int p = 0; p < 8; p++) {
            float4 bs = ((p >> 1) == 0) ? bb0 : ((p >> 1) == 1) ? bb1 : ((p >> 1) == 2) ? bb2 : bb3;
            float4 hr[2];
            #pragma unroll
            for (int s = 0; s < 2; s++) {
                int r = 2 * p + s;
                float dlr = meta[r * 8 + 3], snr = meta[r * 8 + 4];
                float csr = meta[r * 8 + 5], tvr = meta[r * 8 + 6];
                float4 q;
                q.x = fmaf(tvr, wt.x, fmaf(snr, wsn.x, fmaf(csr, wcs.x, fmaf(dlr, wdl.x, bs.x))));
                q.y = fmaf(tvr, wt.y, fmaf(snr, wsn.y, fmaf(csr, wcs.y, fmaf(dlr, wdl.y, bs.y))));
                q.z = fmaf(tvr, wt.z, fmaf(snr, wsn.z, fmaf(csr, wcs.z, fmaf(dlr, wdl.z, bs.z))));
                q.w = fmaf(tvr, wt.w, fmaf(snr, wsn.w, fmaf(csr, wcs.w, fmaf(dlr, wdl.w, bs.w))));
                hr[s] = make_float4(lk(q.x), lk(q.y), lk(q.z), lk(q.w));
            }
            *(float4*)(hp + p * 256 + 8 * lane)     = make_float4(hr[0].x, hr[1].x, hr[0].y, hr[1].y);
            *(float4*)(hp + p * 256 + 8 * lane + 4) = make_float4(hr[0].z, hr[1].z, hr[0].w, hr[1].w);
        }
        __syncwarp();

        // --- layer 1 (packed, 16 rows) ---
        unsigned long long A2[8][4];
        layer_mv2(sm + OFF_W1, hp, lane, b1d, A2);
        __syncwarp();
        #pragma unroll
        for (int p = 0; p < 8; p++) {
            float2 f0 = up2(A2[p][0]), f1 = up2(A2[p][1]);
            float2 f2 = up2(A2[p][2]), f3 = up2(A2[p][3]);
            *(float4*)(hp + p * 256 + 8 * lane)     = make_float4(lk(f0.x), lk(f0.y), lk(f1.x), lk(f1.y));
            *(float4*)(hp + p * 256 + 8 * lane + 4) = make_float4(lk(f2.x), lk(f2.y), lk(f3.x), lk(f3.y));
        }
        __syncwarp();

        // --- layer 2 (packed) ---
        layer_mv2(sm + OFF_W2, hp, lane, b2d, A2);

        // --- layer 3: 128 -> 2 warp reduction per row ---
        #pragma unroll
        for (int p = 0; p < 8; p++) {
            float2 f0 = up2(A2[p][0]), f1 = up2(A2[p][1]);
            float2 f2 = up2(A2[p][2]), f3 = up2(A2[p][3]);
            #pragma unroll
            for (int s = 0; s < 2; s++) {
                int r = 2 * p + s;
                float h0 = lk(s ? f0.y : f0.x), h1 = lk(s ? f1.y : f1.x);
                float h2 = lk(s ? f2.y : f2.x), h3 = lk(s ? f3.y : f3.x);
                float q0 = h0 * w3a.x + h1 * w3a.z + h2 * w3b.x + h3 * w3b.z;
                float q1 = h0 * w3a.y + h1 * w3a.w + h2 * w3b.y + h3 * w3b.w;
                #pragma unroll
                for (int off = 16; off > 0; off >>= 1) {
                    q0 += __shfl_xor_sync(0xffffffffu, q0, off);
                    q1 += __shfl_xor_sync(0xffffffffu, q1, off);
                }
                if (lane == 0) { dbuf[2 * r] = q0 + b30; dbuf[2 * r + 1] = q1 + b31; }
            }
        }
        __syncwarp();

        // --- scatter: 96 atomics (4 propers x 4 t x (2 endpoints x 3 comps)) ---
        #pragma unroll
        for (int a0 = 0; a0 < 96; a0 += 32) {
            int a = a0 + lane;
            int row = a / 6; int w6 = a - row * 6;
            int q = row >> 2, tt = row & 3;
            int4 Ps = (q == 0) ? P0 : (q == 1) ? P1 : (q == 2) ? P2 : P3;
            int comp = (w6 < 3) ? w6 : (w6 - 3);
            int tgt = (w6 < 3) ? Ps.x : Ps.w;
            float dval = (w6 < 3) ? (-0.5f * dbuf[2 * row]) : (0.5f * dbuf[2 * row + 1]);
            atomicAdd(out + (tgt * 4 + tt) * 3 + comp, dval * meta[row * 8 + comp]);
        }
        __syncwarp();
    }
}

extern "C" void kernel_launch(void* const* d_in, const int* in_sizes, int n_in,
                              void* d_out, int out_size)
{
    const float* coords  = (const float*)d_in[0];
    const int*   propers = (const int*)d_in[1];     // int32 (JAX x64 off)
    const float* encoded = (const float*)d_in[2];
    const float* tarr    = (const float*)d_in[3];
    const float* answer  = (const float*)d_in[4];
    const float* W0 = (const float*)d_in[5];
    const float* b0 = (const float*)d_in[6];
    const float* W1 = (const float*)d_in[7];
    const float* b1 = (const float*)d_in[8];
    const float* W2 = (const float*)d_in[9];
    const float* b2 = (const float*)d_in[10];
    const float* W3 = (const float*)d_in[11];
    const float* b3 = (const float*)d_in[12];
    float* out = (float*)d_out;

    int dev = 0;
    cudaGetDevice(&dev);
    int sms = 148;
    cudaDeviceGetAttribute(&sms, cudaDevAttrMultiProcessorCount, dev);

    cudaFuncSetAttribute(main_kernel, cudaFuncAttributeMaxDynamicSharedMemorySize,
                         SMEM_FLOATS * (int)sizeof(float));

    // out = answer (atomics accumulate on top)
    cudaMemcpyAsync(d_out, answer, (size_t)out_size * sizeof(float),
                    cudaMemcpyDeviceToDevice);

    dim3 eg((NN + 31) / 32, 4);
    epre_kernel<<<eg, 256>>>(encoded, W0);

    main_kernel<<<sms, 256, SMEM_FLOATS * (int)sizeof(float)>>>(
        coords, propers, tarr, W0, b0, W1, b1, W2, b2, W3, b3, out);
}